// round 5
// baseline (speedup 1.0000x reference)
#include <cuda_runtime.h>

#define B_     8
#define HEADS  8
#define D_     128
#define DH     64                 // d's per k1 CTA (d-split)
#define R_     8
#define S_     4096
#define S4     (S_ / 4)
#define NSLAB  (B_ * HEADS)       // 64
#define TILES  8
#define TILE_S (S_ / TILES)       // 512
#define PF     4                  // k1 load-pipeline depth

// ---------------- scratch ----------------
__device__ float g_m[2 * (size_t)NSLAB * S_ * R_];  // [half][slab][s][r]  16 MB
__device__ float g_colp[NSLAB * TILES * D_];        // per-tile partial column sums
__device__ float g_k[NSLAB * R_];
__device__ float g_c[NSLAB];
__device__ float g_v[NSLAB * D_];                   // index == global output row
__device__ float g_eattn[NSLAB * S_];               // unnormalized exp per tile, 1 MB
__device__ float g_pmax[NSLAB * TILES];
__device__ float g_psum[NSLAB * TILES];

// packed f32x2 helpers
__device__ __forceinline__ float2 ffma2(float2 a, float2 b, float2 c) {
    unsigned long long ua = *reinterpret_cast<unsigned long long*>(&a);
    unsigned long long ub = *reinterpret_cast<unsigned long long*>(&b);
    unsigned long long uc = *reinterpret_cast<unsigned long long*>(&c);
    unsigned long long ud;
    asm("fma.rn.f32x2 %0, %1, %2, %3;" : "=l"(ud) : "l"(ua), "l"(ub), "l"(uc));
    return *reinterpret_cast<float2*>(&ud);
}
__device__ __forceinline__ float2 fadd2(float2 a, float2 b) {
    unsigned long long ua = *reinterpret_cast<unsigned long long*>(&a);
    unsigned long long ub = *reinterpret_cast<unsigned long long*>(&b);
    unsigned long long ud;
    asm("add.rn.f32x2 %0, %1, %2;" : "=l"(ud) : "l"(ua), "l"(ub));
    return *reinterpret_cast<float2*>(&ud);
}

// =======================================================================================
// K1: pass over x, d-split: CTA = (slab, tile, half). half owns d in [half*64, half*64+64).
// Produces partial m (its d-range's contribution) + column-sum partials for its d's.
// 1024 CTAs x 128 threads.
// =======================================================================================
__global__ void __launch_bounds__(128, 6) k1_proj(const float* __restrict__ x,
                                                  const float* __restrict__ Wq)
{
    const int cta  = blockIdx.x;
    const int slab = cta >> 4;
    const int tile = (cta >> 1) & 7;
    const int half = cta & 1;
    const int h    = slab & (HEADS - 1);
    const int d0   = half * DH;
    const int t    = threadIdx.x;
    const int lane = t & 31;
    const int w    = t >> 5;

    __shared__ __align__(16) float2 s_wq[DH * R_];  // duplicated pairs, 4 KB
    __shared__ float s_part[DH * 33];               // padded partials, 8.4 KB

    const float* wqh = Wq + (size_t)h * R_ * D_;
    if (t < DH) {
        #pragma unroll
        for (int r = 0; r < R_; r++) {
            float wv = wqh[r * D_ + d0 + t];
            s_wq[t * R_ + r] = make_float2(wv, wv);
        }
    }
    __syncthreads();

    const float4* __restrict__ xb =
        (const float4*)x + (size_t)slab * D_ * S4 + (size_t)d0 * S4 + tile * (TILE_S / 4);

    float2 alo[R_], ahi[R_];
    #pragma unroll
    for (int r = 0; r < R_; r++) { alo[r] = make_float2(0.f, 0.f); ahi[r] = make_float2(0.f, 0.f); }

#define K1_PROCESS(xv_, d_)                                                      \
    {                                                                            \
        float2 xl = make_float2((xv_).x, (xv_).y);                               \
        float2 xh = make_float2((xv_).z, (xv_).w);                               \
        const float4* wrow = (const float4*)(s_wq + (d_) * R_);                  \
        _Pragma("unroll")                                                        \
        for (int j = 0; j < 4; j++) {                                            \
            float4 wp = wrow[j];                                                 \
            float2 w0 = make_float2(wp.x, wp.y);                                 \
            float2 w1 = make_float2(wp.z, wp.w);                                 \
            alo[2*j]   = ffma2(w0, xl, alo[2*j]);                                \
            ahi[2*j]   = ffma2(w0, xh, ahi[2*j]);                                \
            alo[2*j+1] = ffma2(w1, xl, alo[2*j+1]);                              \
            ahi[2*j+1] = ffma2(w1, xh, ahi[2*j+1]);                              \
        }                                                                        \
        float2 rp = fadd2(xl, xh);                                               \
        float rs = rp.x + rp.y;                                                  \
        rs += __shfl_xor_sync(0xffffffffu, rs, 16);                              \
        rs += __shfl_xor_sync(0xffffffffu, rs, 8);                               \
        if (lane < 8) s_part[(d_) * 33 + w * 8 + lane] = rs;                     \
    }

    float4 buf[PF];
    #pragma unroll
    for (int j = 0; j < PF; j++) buf[j] = xb[j * S4 + t];

    #pragma unroll 1
    for (int db = 0; db < DH - PF; db += PF) {
        #pragma unroll
        for (int j = 0; j < PF; j++) {
            float4 xv = buf[j];
            buf[j] = xb[(db + PF + j) * S4 + t];
            K1_PROCESS(xv, db + j);
        }
    }
    #pragma unroll
    for (int j = 0; j < PF; j++) {
        float4 xv = buf[j];
        K1_PROCESS(xv, (DH - PF) + j);
    }
#undef K1_PROCESS

    __syncthreads();

    // finalize this (tile, half)'s column sums: thread t < 64 handles dlocal = t
    if (t < DH) {
        float s = 0.f;
        #pragma unroll
        for (int i = 0; i < 32; i++) s += s_part[t * 33 + i];
        g_colp[(slab * TILES + tile) * D_ + d0 + t] = s;
    }

    // write partial m: [half][slab][s][r]
    float4* m4 = (float4*)(g_m +
        (((size_t)half * NSLAB + slab) * S_ + (size_t)tile * TILE_S + t * 4) * R_);
    m4[0] = make_float4(alo[0].x, alo[1].x, alo[2].x, alo[3].x);
    m4[1] = make_float4(alo[4].x, alo[5].x, alo[6].x, alo[7].x);
    m4[2] = make_float4(alo[0].y, alo[1].y, alo[2].y, alo[3].y);
    m4[3] = make_float4(alo[4].y, alo[5].y, alo[6].y, alo[7].y);
    m4[4] = make_float4(ahi[0].x, ahi[1].x, ahi[2].x, ahi[3].x);
    m4[5] = make_float4(ahi[4].x, ahi[5].x, ahi[6].x, ahi[7].x);
    m4[6] = make_float4(ahi[0].y, ahi[1].y, ahi[2].y, ahi[3].y);
    m4[7] = make_float4(ahi[4].y, ahi[5].y, ahi[6].y, ahi[7].y);
}

// =======================================================================================
// K2: per-slab tiny GEMVs: avg -> k[8], c, v[128]. 64 CTAs x 128 threads.
// =======================================================================================
__global__ void __launch_bounds__(128) k2_kv(const float* __restrict__ Wq,
                                             const float* __restrict__ bq,
                                             const float* __restrict__ Wk,
                                             const float* __restrict__ bk,
                                             const float* __restrict__ Wv,
                                             const float* __restrict__ bv)
{
    const int slab = blockIdx.x;
    const int h    = slab & (HEADS - 1);
    const int t    = threadIdx.x;
    const int lane = t & 31;
    const int w    = t >> 5;

    __shared__ __align__(16) float s_avg[D_];
    __shared__ float s_k[R_];

    {
        float a = 0.f;
        #pragma unroll
        for (int i = 0; i < TILES; i++) a += g_colp[(slab * TILES + i) * D_ + t];
        s_avg[t] = a * (1.0f / (float)S_);
    }
    __syncthreads();

    const float4 av = ((const float4*)s_avg)[lane];

    for (int i = 0; i < 32; i++) {
        int e = w * 32 + i;
        float4 wv = ((const float4*)(Wv + ((size_t)h * D_ + e) * D_))[lane];
        float p = av.x * wv.x + av.y * wv.y + av.z * wv.z + av.w * wv.w;
        p += __shfl_xor_sync(0xffffffffu, p, 16);
        p += __shfl_xor_sync(0xffffffffu, p, 8);
        p += __shfl_xor_sync(0xffffffffu, p, 4);
        p += __shfl_xor_sync(0xffffffffu, p, 2);
        p += __shfl_xor_sync(0xffffffffu, p, 1);
        if (lane == 0) g_v[slab * D_ + e] = p + bv[h * D_ + e];
    }

    if (w == 0) {
        for (int r = 0; r < R_; r++) {
            float4 wk = ((const float4*)(Wk + ((size_t)h * R_ + r) * D_))[lane];
            float p = av.x * wk.x + av.y * wk.y + av.z * wk.z + av.w * wk.w;
            p += __shfl_xor_sync(0xffffffffu, p, 16);
            p += __shfl_xor_sync(0xffffffffu, p, 8);
            p += __shfl_xor_sync(0xffffffffu, p, 4);
            p += __shfl_xor_sync(0xffffffffu, p, 2);
            p += __shfl_xor_sync(0xffffffffu, p, 1);
            if (lane == 0) s_k[r] = p + bk[h * R_ + r];
        }
        if (lane == 0) {
            float c = 0.f;
            #pragma unroll
            for (int r = 0; r < R_; r++) {
                float kv = s_k[r];
                c += bq[h * R_ + r] * kv;
                g_k[slab * R_ + r] = kv;
            }
            g_c[slab] = c;
        }
    }
}

// =======================================================================================
// K3: sum m halves; scores = m.k + c; per-tile max; write UNNORMALIZED exp + tile stats.
// 512 CTAs x 128 threads (thread owns 4 consecutive s).
// =======================================================================================
__global__ void __launch_bounds__(128) k3_scores()
{
    const int slab = blockIdx.x >> 3;
    const int tile = blockIdx.x & 7;
    const int t    = threadIdx.x;
    const int lane = t & 31;
    const int w    = t >> 5;

    __shared__ float redm[4];
    __shared__ float reds[4];
    __shared__ float s_bmx;

    const float* kk = g_k + slab * R_;
    const float k0 = kk[0], k1 = kk[1], k2 = kk[2], k3 = kk[3];
    const float k4 = kk[4], k5 = kk[5], k6 = kk[6], k7 = kk[7];
    const float c  = g_c[slab];

    const size_t soff = (size_t)tile * TILE_S + t * 4;
    const float4* mA = (const float4*)(g_m + ((size_t)slab * S_ + soff) * R_);
    const float4* mB = mA + (size_t)NSLAB * S_ * (R_ / 4);

    float sc[4];
    float mx = -3.4e38f;
    #pragma unroll
    for (int i = 0; i < 4; i++) {
        float4 a0 = mA[i * 2],     b0 = mB[i * 2];
        float4 a1 = mA[i * 2 + 1], b1 = mB[i * 2 + 1];
        float v = c + k0 * (a0.x + b0.x) + k1 * (a0.y + b0.y)
                    + k2 * (a0.z + b0.z) + k3 * (a0.w + b0.w)
                    + k4 * (a1.x + b1.x) + k5 * (a1.y + b1.y)
                    + k6 * (a1.z + b1.z) + k7 * (a1.w + b1.w);
        sc[i] = v;
        mx = fmaxf(mx, v);
    }
    #pragma unroll
    for (int o = 16; o; o >>= 1) mx = fmaxf(mx, __shfl_xor_sync(0xffffffffu, mx, o));
    if (lane == 0) redm[w] = mx;
    __syncthreads();
    if (t == 0) s_bmx = fmaxf(fmaxf(redm[0], redm[1]), fmaxf(redm[2], redm[3]));
    __syncthreads();
    const float bmx = s_bmx;

    float4 ev;
    ev.x = __expf(sc[0] - bmx); ev.y = __expf(sc[1] - bmx);
    ev.z = __expf(sc[2] - bmx); ev.w = __expf(sc[3] - bmx);
    float tot = (ev.x + ev.y) + (ev.z + ev.w);
    #pragma unroll
    for (int o = 16; o; o >>= 1) tot += __shfl_xor_sync(0xffffffffu, tot, o);
    if (lane == 0) reds[w] = tot;

    ((float4*)(g_eattn + (size_t)slab * S_ + soff))[0] = ev;

    __syncthreads();
    if (t == 0) {
        g_pmax[slab * TILES + tile] = bmx;
        g_psum[slab * TILES + tile] = (reds[0] + reds[1]) + (reds[2] + reds[3]);
    }
}

// =======================================================================================
// K4: CTA = (slab, tile of 512 s). attn chunk (scaled) held in regs; loop 128 rows.
// Write-through stores so L2 is left clean for the next replay's k1.
// 512 CTAs x 256 threads.
// =======================================================================================
__global__ void __launch_bounds__(256) k4_out(float* __restrict__ out)
{
    const int slab = blockIdx.x >> 3;
    const int tile = blockIdx.x & 7;
    const int t    = threadIdx.x;
    const int col  = t & 127;         // float4 column within the 512-s chunk
    const int grp  = t >> 7;          // 0 or 1: row parity

    __shared__ float s_v[D_];
    __shared__ float s_scale;

    if (t < D_) s_v[t] = g_v[slab * D_ + t];
    if (t == 0) {
        float pm[TILES];
        float gmax = -3.4e38f;
        #pragma unroll
        for (int i = 0; i < TILES; i++) {
            pm[i] = g_pmax[slab * TILES + i];
            gmax = fmaxf(gmax, pm[i]);
        }
        float tot = 0.f;
        #pragma unroll
        for (int i = 0; i < TILES; i++)
            tot += g_psum[slab * TILES + i] * __expf(pm[i] - gmax);
        s_scale = __expf(pm[tile] - gmax) / tot;
    }
    __syncthreads();

    const float sc = s_scale;
    float4 a = ((const float4*)(g_eattn + (size_t)slab * S_ + tile * TILE_S))[col];
    a.x *= sc; a.y *= sc; a.z *= sc; a.w *= sc;

    // out float4 base for this slab/tile
    float4* o4 = (float4*)out + ((size_t)slab * D_) * (S_ / 4) + tile * (TILE_S / 4) + col;

    #pragma unroll 4
    for (int i = 0; i < 64; i++) {
        int row = i * 2 + grp;
        float vv = s_v[row];
        __stwt(&o4[(size_t)row * S4],
               make_float4(vv * a.x, vv * a.y, vv * a.z, vv * a.w));
    }
}

// =======================================================================================
extern "C" void kernel_launch(void* const* d_in, const int* in_sizes, int n_in,
                              void* d_out, int out_size)
{
    const float* x  = (const float*)d_in[0];
    const float* Wq = (const float*)d_in[1];
    const float* bq = (const float*)d_in[2];
    const float* Wk = (const float*)d_in[3];
    const float* bk = (const float*)d_in[4];
    const float* Wv = (const float*)d_in[5];
    const float* bv = (const float*)d_in[6];
    float* out = (float*)d_out;

    k1_proj<<<NSLAB * TILES * 2, 128>>>(x, Wq);
    k2_kv<<<NSLAB, 128>>>(Wq, bq, Wk, bk, Wv, bv);
    k3_scores<<<NSLAB * TILES, 128>>>();
    k4_out<<<NSLAB * TILES, 256>>>(out);
}

// round 6
// speedup vs baseline: 1.5060x; 1.5060x over previous
#include <cuda_runtime.h>

#define B_     8
#define HEADS  8
#define D_     128
#define DH     64                 // d's per k1 CTA (d-split)
#define R_     8
#define S_     4096
#define S4     (S_ / 4)
#define NSLAB  (B_ * HEADS)       // 64
#define TILES  8
#define TILE_S (S_ / TILES)       // 512
#define PF     4                  // k1 load-pipeline depth

// ---------------- scratch ----------------
__device__ float g_m[2 * (size_t)NSLAB * S_ * R_];  // [half][slab][s][r]  16 MB
__device__ float g_colp[NSLAB * TILES * D_];        // per-tile partial column sums
__device__ float g_k[NSLAB * R_];
__device__ float g_c[NSLAB];
__device__ float g_v[NSLAB * D_];                   // index == global output row
__device__ float g_eattn[NSLAB * S_];               // unnormalized exp per tile, 1 MB
__device__ float g_pmax[NSLAB * TILES];
__device__ float g_psum[NSLAB * TILES];

// packed f32x2 helpers
__device__ __forceinline__ float2 ffma2(float2 a, float2 b, float2 c) {
    unsigned long long ua = *reinterpret_cast<unsigned long long*>(&a);
    unsigned long long ub = *reinterpret_cast<unsigned long long*>(&b);
    unsigned long long uc = *reinterpret_cast<unsigned long long*>(&c);
    unsigned long long ud;
    asm("fma.rn.f32x2 %0, %1, %2, %3;" : "=l"(ud) : "l"(ua), "l"(ub), "l"(uc));
    return *reinterpret_cast<float2*>(&ud);
}
__device__ __forceinline__ float2 fadd2(float2 a, float2 b) {
    unsigned long long ua = *reinterpret_cast<unsigned long long*>(&a);
    unsigned long long ub = *reinterpret_cast<unsigned long long*>(&b);
    unsigned long long ud;
    asm("add.rn.f32x2 %0, %1, %2;" : "=l"(ud) : "l"(ua), "l"(ub));
    return *reinterpret_cast<float2*>(&ud);
}

// =======================================================================================
// K1: pass over x, d-split: CTA = (slab, tile, half). half owns d in [half*64, half*64+64).
// Partial m contribution + column-sum partials for its d's. 1024 CTAs x 128 threads.
// NO min-blocks launch bound: must not spill the ~70-reg working set.
// =======================================================================================
__global__ void __launch_bounds__(128) k1_proj(const float* __restrict__ x,
                                               const float* __restrict__ Wq)
{
    const int cta  = blockIdx.x;
    const int slab = cta >> 4;
    const int tile = (cta >> 1) & 7;
    const int half = cta & 1;
    const int h    = slab & (HEADS - 1);
    const int d0   = half * DH;
    const int t    = threadIdx.x;
    const int lane = t & 31;
    const int w    = t >> 5;

    __shared__ __align__(16) float2 s_wq[DH * R_];  // duplicated pairs, 4 KB
    __shared__ float s_part[DH * 33];               // padded partials, 8.4 KB

    const float* wqh = Wq + (size_t)h * R_ * D_;
    if (t < DH) {
        #pragma unroll
        for (int r = 0; r < R_; r++) {
            float wv = wqh[r * D_ + d0 + t];
            s_wq[t * R_ + r] = make_float2(wv, wv);
        }
    }
    __syncthreads();

    const float4* __restrict__ xb =
        (const float4*)x + (size_t)slab * D_ * S4 + (size_t)d0 * S4 + tile * (TILE_S / 4);

    float2 alo[R_], ahi[R_];
    #pragma unroll
    for (int r = 0; r < R_; r++) { alo[r] = make_float2(0.f, 0.f); ahi[r] = make_float2(0.f, 0.f); }

#define K1_PROCESS(xv_, d_)                                                      \
    {                                                                            \
        float2 xl = make_float2((xv_).x, (xv_).y);                               \
        float2 xh = make_float2((xv_).z, (xv_).w);                               \
        const float4* wrow = (const float4*)(s_wq + (d_) * R_);                  \
        _Pragma("unroll")                                                        \
        for (int j = 0; j < 4; j++) {                                            \
            float4 wp = wrow[j];                                                 \
            float2 w0 = make_float2(wp.x, wp.y);                                 \
            float2 w1 = make_float2(wp.z, wp.w);                                 \
            alo[2*j]   = ffma2(w0, xl, alo[2*j]);                                \
            ahi[2*j]   = ffma2(w0, xh, ahi[2*j]);                                \
            alo[2*j+1] = ffma2(w1, xl, alo[2*j+1]);                              \
            ahi[2*j+1] = ffma2(w1, xh, ahi[2*j+1]);                              \
        }                                                                        \
        float2 rp = fadd2(xl, xh);                                               \
        float rs = rp.x + rp.y;                                                  \
        rs += __shfl_xor_sync(0xffffffffu, rs, 16);                              \
        rs += __shfl_xor_sync(0xffffffffu, rs, 8);                               \
        if (lane < 8) s_part[(d_) * 33 + w * 8 + lane] = rs;                     \
    }

    float4 buf[PF];
    #pragma unroll
    for (int j = 0; j < PF; j++) buf[j] = xb[j * S4 + t];

    #pragma unroll 1
    for (int db = 0; db < DH - PF; db += PF) {
        #pragma unroll
        for (int j = 0; j < PF; j++) {
            float4 xv = buf[j];
            buf[j] = xb[(db + PF + j) * S4 + t];
            K1_PROCESS(xv, db + j);
        }
    }
    #pragma unroll
    for (int j = 0; j < PF; j++) {
        float4 xv = buf[j];
        K1_PROCESS(xv, (DH - PF) + j);
    }
#undef K1_PROCESS

    __syncthreads();

    if (t < DH) {
        float s = 0.f;
        #pragma unroll
        for (int i = 0; i < 32; i++) s += s_part[t * 33 + i];
        g_colp[(slab * TILES + tile) * D_ + d0 + t] = s;
    }

    // write partial m: [half][slab][s][r]
    float4* m4 = (float4*)(g_m +
        (((size_t)half * NSLAB + slab) * S_ + (size_t)tile * TILE_S + t * 4) * R_);
    m4[0] = make_float4(alo[0].x, alo[1].x, alo[2].x, alo[3].x);
    m4[1] = make_float4(alo[4].x, alo[5].x, alo[6].x, alo[7].x);
    m4[2] = make_float4(alo[0].y, alo[1].y, alo[2].y, alo[3].y);
    m4[3] = make_float4(alo[4].y, alo[5].y, alo[6].y, alo[7].y);
    m4[4] = make_float4(ahi[0].x, ahi[1].x, ahi[2].x, ahi[3].x);
    m4[5] = make_float4(ahi[4].x, ahi[5].x, ahi[6].x, ahi[7].x);
    m4[6] = make_float4(ahi[0].y, ahi[1].y, ahi[2].y, ahi[3].y);
    m4[7] = make_float4(ahi[4].y, ahi[5].y, ahi[6].y, ahi[7].y);
}

// =======================================================================================
// K2: per-slab: avg -> k[8], c, v[128]. 64 CTAs x 128 threads.
// Per-thread dot products against smem avg — no shuffle chains, no serial row loops.
// =======================================================================================
__global__ void __launch_bounds__(128) k2_kv(const float* __restrict__ Wq,
                                             const float* __restrict__ bq,
                                             const float* __restrict__ Wk,
                                             const float* __restrict__ bk,
                                             const float* __restrict__ Wv,
                                             const float* __restrict__ bv)
{
    const int slab = blockIdx.x;
    const int h    = slab & (HEADS - 1);
    const int t    = threadIdx.x;

    __shared__ __align__(16) float s_avg[D_];
    __shared__ float s_k[R_];
    __shared__ float s_c;

    {
        float a = 0.f;
        #pragma unroll
        for (int i = 0; i < TILES; i++) a += g_colp[(slab * TILES + i) * D_ + t];
        s_avg[t] = a * (1.0f / (float)S_);
    }
    __syncthreads();

    // v[e=t] = dot(avg, Wv[h,t,:]) + bv[h,t]   (thread-private dot, float4 unrolled)
    {
        const float4* wr = (const float4*)(Wv + ((size_t)h * D_ + t) * D_);
        const float4* ar = (const float4*)s_avg;
        float acc = 0.f;
        #pragma unroll 8
        for (int i = 0; i < D_ / 4; i++) {
            float4 wv = wr[i];
            float4 av = ar[i];
            acc += av.x * wv.x + av.y * wv.y + av.z * wv.z + av.w * wv.w;
        }
        g_v[slab * D_ + t] = acc + bv[h * D_ + t];
    }

    // k[r=t<8] = dot(avg, Wk[h,t,:]) + bk[h,t]
    if (t < R_) {
        const float4* wr = (const float4*)(Wk + ((size_t)h * R_ + t) * D_);
        const float4* ar = (const float4*)s_avg;
        float acc = 0.f;
        #pragma unroll 8
        for (int i = 0; i < D_ / 4; i++) {
            float4 wv = wr[i];
            float4 av = ar[i];
            acc += av.x * wv.x + av.y * wv.y + av.z * wv.z + av.w * wv.w;
        }
        float kv = acc + bk[h * R_ + t];
        s_k[t] = kv;
        g_k[slab * R_ + t] = kv;
    }
    __syncthreads();
    if (t == 0) {
        float c = 0.f;
        #pragma unroll
        for (int r = 0; r < R_; r++) c += bq[h * R_ + r] * s_k[r];
        g_c[slab] = c;
        s_c = c;
    }
}

// =======================================================================================
// K3: sum m halves; scores = m.k + c; per-tile max; write UNNORMALIZED exp + tile stats.
// 512 CTAs x 128 threads (thread owns 4 consecutive s).
// =======================================================================================
__global__ void __launch_bounds__(128) k3_scores()
{
    const int slab = blockIdx.x >> 3;
    const int tile = blockIdx.x & 7;
    const int t    = threadIdx.x;
    const int lane = t & 31;
    const int w    = t >> 5;

    __shared__ float redm[4];
    __shared__ float reds[4];
    __shared__ float s_bmx;

    const float* kk = g_k + slab * R_;
    const float k0 = kk[0], k1 = kk[1], k2 = kk[2], k3 = kk[3];
    const float k4 = kk[4], k5 = kk[5], k6 = kk[6], k7 = kk[7];
    const float c  = g_c[slab];

    const size_t soff = (size_t)tile * TILE_S + t * 4;
    const float4* mA = (const float4*)(g_m + ((size_t)slab * S_ + soff) * R_);
    const float4* mB = mA + (size_t)NSLAB * S_ * (R_ / 4);

    float sc[4];
    float mx = -3.4e38f;
    #pragma unroll
    for (int i = 0; i < 4; i++) {
        float4 a0 = mA[i * 2],     b0 = mB[i * 2];
        float4 a1 = mA[i * 2 + 1], b1 = mB[i * 2 + 1];
        float v = c + k0 * (a0.x + b0.x) + k1 * (a0.y + b0.y)
                    + k2 * (a0.z + b0.z) + k3 * (a0.w + b0.w)
                    + k4 * (a1.x + b1.x) + k5 * (a1.y + b1.y)
                    + k6 * (a1.z + b1.z) + k7 * (a1.w + b1.w);
        sc[i] = v;
        mx = fmaxf(mx, v);
    }
    #pragma unroll
    for (int o = 16; o; o >>= 1) mx = fmaxf(mx, __shfl_xor_sync(0xffffffffu, mx, o));
    if (lane == 0) redm[w] = mx;
    __syncthreads();
    if (t == 0) s_bmx = fmaxf(fmaxf(redm[0], redm[1]), fmaxf(redm[2], redm[3]));
    __syncthreads();
    const float bmx = s_bmx;

    float4 ev;
    ev.x = __expf(sc[0] - bmx); ev.y = __expf(sc[1] - bmx);
    ev.z = __expf(sc[2] - bmx); ev.w = __expf(sc[3] - bmx);
    float tot = (ev.x + ev.y) + (ev.z + ev.w);
    #pragma unroll
    for (int o = 16; o; o >>= 1) tot += __shfl_xor_sync(0xffffffffu, tot, o);
    if (lane == 0) reds[w] = tot;

    ((float4*)(g_eattn + (size_t)slab * S_ + soff))[0] = ev;

    __syncthreads();
    if (t == 0) {
        g_pmax[slab * TILES + tile] = bmx;
        g_psum[slab * TILES + tile] = (reds[0] + reds[1]) + (reds[2] + reds[3]);
    }
}

// =======================================================================================
// K4: out[row,s] = v[row] * scale[tile(s)] * eattn[slab,s]. 8192 CTAs x 256 threads.
// =======================================================================================
__global__ void __launch_bounds__(256) k4_out(float* __restrict__ out)
{
    const int row  = blockIdx.x;
    const int slab = row >> 7;
    const int t    = threadIdx.x;

    __shared__ float s_scale[TILES];

    const float v = g_v[row];

    if (t < TILES) {
        float pm[TILES];
        float gmax = -3.4e38f;
        #pragma unroll
        for (int i = 0; i < TILES; i++) {
            pm[i] = g_pmax[slab * TILES + i];
            gmax = fmaxf(gmax, pm[i]);
        }
        float tot = 0.f;
        #pragma unroll
        for (int i = 0; i < TILES; i++)
            tot += g_psum[slab * TILES + i] * __expf(pm[i] - gmax);
        s_scale[t] = __expf(pm[t] - gmax) / tot;
    }
    __syncthreads();

    const float4* a4 = (const float4*)(g_eattn + (size_t)slab * S_);
    float4* o4 = (float4*)(out + (size_t)row * S_);

    #pragma unroll
    for (int i = 0; i < 4; i++) {
        float sc = v * s_scale[2 * i + (t >> 7)];
        float4 a = __ldg(&a4[i * 256 + t]);
        __stcs(&o4[i * 256 + t],
               make_float4(sc * a.x, sc * a.y, sc * a.z, sc * a.w));
    }
}

// =======================================================================================
extern "C" void kernel_launch(void* const* d_in, const int* in_sizes, int n_in,
                              void* d_out, int out_size)
{
    const float* x  = (const float*)d_in[0];
    const float* Wq = (const float*)d_in[1];
    const float* bq = (const float*)d_in[2];
    const float* Wk = (const float*)d_in[3];
    const float* bk = (const float*)d_in[4];
    const float* Wv = (const float*)d_in[5];
    const float* bv = (const float*)d_in[6];
    float* out = (float*)d_out;

    k1_proj<<<NSLAB * TILES * 2, 128>>>(x, Wq);
    k2_kv<<<NSLAB, 128>>>(Wq, bq, Wk, bk, Wv, bv);
    k3_scores<<<NSLAB * TILES, 128>>>();
    k4_out<<<B_ * 1024, 256>>>(out);
}